// round 17
// baseline (speedup 1.0000x reference)
#include <cuda_runtime.h>
#include <cuda_bf16.h>

// RKN scan R17: TWO batches per CTA (grid 64, 256 thr). Each batch: 128
// threads, one per row, ALL 7 diagonals per thread (R9 scheme), per-batch
// named barrier (1/step), double-buffered state+red. Tables: d0,d1,d2,d4
// bf16 in regs; fp32 diag + d5,d6 bf16 in smem SHARED by both batches.

#define NB   128
#define NT   128
#define NLOD 128
#define NK   16

// dynamic smem layout (bytes)
static constexpr int DG_OFF  = 0;                        // float4[NK*NLOD] diag fp32
static constexpr int OD_OFF  = DG_OFF + NK * NLOD * 16;  // uint4[NK*NLOD] d5,d6
static constexpr int ST_OFF  = OD_OFF + NK * NLOD * 16;  // float4[2][2][136]
static constexpr int CS_OFF  = ST_OFF + 4 * 136 * 16;    // float[2][2][136]
static constexpr int RED_OFF = CS_OFF + 4 * 136 * 4;     // float[2][2][64]
static constexpr int SMEM_BYTES = RED_OFF + 4 * 64 * 4;  // ~77.4 KB

__device__ __forceinline__ unsigned int pk(float a, float b) {
    __nv_bfloat162 t = __floats2bfloat162_rn(a, b);
    return reinterpret_cast<unsigned int&>(t);
}
// acc(f32x2) += { lo: p<<16 (exact), hi: raw p (garbage low mantissa) } * {a,a}
__device__ __forceinline__ void pair_fma(unsigned long long& acc,
                                         unsigned int p, unsigned long long a2) {
    asm("{\n\t.reg .b32 lo;\n\t.reg .b64 v;\n\t"
        "shl.b32 lo, %1, 16;\n\t"
        "mov.b64 v, {lo, %1};\n\t"
        "fma.rn.f32x2 %0, v, %2, %0;\n\t}"
        : "+l"(acc) : "r"(p), "l"(a2));
}
__device__ __forceinline__ unsigned long long dup2(float a) {
    unsigned long long r;
    asm("mov.b64 %0, {%1, %1};" : "=l"(r) : "f"(a));
    return r;
}
__device__ __forceinline__ void unpk2(unsigned long long r, float& x, float& y) {
    asm("mov.b64 {%0, %1}, %2;" : "=f"(x), "=f"(y) : "l"(r));
}
__device__ __forceinline__ float frcp(float x) {
    float r;
    asm("rcp.approx.f32 %0, %1;" : "=f"(r) : "f"(x));
    return r;
}
__device__ __forceinline__ void bar128(int id) {
    asm volatile("bar.sync %0, 128;" :: "r"(id) : "memory");
}

#define RED_ROUND(m)                                                          \
  _Pragma("unroll")                                                           \
  for (int k = 0; k < (m); k++) {                                             \
    float a_ = v[k], c_ = v[k + (m)];                                         \
    bool  hi_ = (lane & (m)) != 0;                                            \
    float keep_ = hi_ ? c_ : a_;                                              \
    float send_ = hi_ ? a_ : c_;                                              \
    v[k] = keep_ + __shfl_xor_sync(0xffffffffu, send_, (m));                  \
  }

// normalize by inv, then accumulate one diagonal's matvec contribution
#define BAND_NORM_ACC(d, A11, A12, A21, A22)                                  \
  {                                                                           \
    float a11 = (A11) * inv, a12 = (A12) * inv;                               \
    float a21 = (A21) * inv, a22 = (A22) * inv;                               \
    float4 st_ = stb[r + (d)];                                                \
    float  csj = csb[r + (d)];                                                \
    float muj = st_.x, mlj = st_.y, cuj = st_.z, clj = st_.w;                 \
    nmu = fmaf(a11, muj, nmu); nmu = fmaf(a12, mlj, nmu);                     \
    nml = fmaf(a21, muj, nml); nml = fmaf(a22, mlj, nml);                     \
    ncu = fmaf(a11 * a11, cuj, ncu);                                          \
    ncu = fmaf(2.0f * a11 * a12, csj, ncu);                                   \
    ncu = fmaf(a12 * a12, clj, ncu);                                          \
    ncl = fmaf(a21 * a21, cuj, ncl);                                          \
    ncl = fmaf(2.0f * a21 * a22, csj, ncl);                                   \
    ncl = fmaf(a22 * a22, clj, ncl);                                          \
    ncs = fmaf(a21 * a11, cuj, ncs);                                          \
    ncs = fmaf(fmaf(a22, a11, a21 * a12), csj, ncs);                          \
    ncs = fmaf(a22 * a12, clj, ncs);                                          \
  }

__global__ void __launch_bounds__(256, 1)
rkn_kernel(const float* __restrict__ lobs,   // (B,T,LOD)
           const float* __restrict__ ovars,  // (B,T,LOD)
           const float* __restrict__ imean,  // (B,2*LOD)
           const float* __restrict__ icu,
           const float* __restrict__ icl,
           const float* __restrict__ ics,
           const float* __restrict__ tm11,   // (K,LOD,LOD)
           const float* __restrict__ tm12,
           const float* __restrict__ tm21,
           const float* __restrict__ tm22,
           const float* __restrict__ cw,     // (2*LOD, K)
           const float* __restrict__ cb,     // (K,)
           const float* __restrict__ tcu,
           const float* __restrict__ tcl,
           float* __restrict__ out)
{
    extern __shared__ char smraw[];
    float4* dg   = reinterpret_cast<float4*>(smraw + DG_OFF);
    uint4*  od   = reinterpret_cast<uint4*>(smraw + OD_OFF);
    float4* s_st = reinterpret_cast<float4*>(smraw + ST_OFF);   // [half][2][136]
    float*  s_cs = reinterpret_cast<float*>(smraw + CS_OFF);    // [half][2][136]
    float*  red  = reinterpret_cast<float*>(smraw + RED_OFF);   // [half][2][64]

    const int tid  = threadIdx.x;
    const int lane = tid & 31;
    const int wloc = (tid >> 5) & 3;   // warp index within the batch (0..3)
    const int half = tid >> 7;         // which batch slot
    const int r    = tid & 127;        // row
    const int b    = (blockIdx.x << 1) + half;
    const int barid = 1 + half;

    // ---- prologue: shared smem tables (all 256 threads) ----
    for (int rr = tid; rr < NK * NLOD; rr += 256) {
        int k = rr >> 7, ii = rr & 127;
        long base = ((long)k * NLOD + ii) * NLOD;
        dg[rr] = make_float4(__ldg(tm11 + base + ii), __ldg(tm12 + base + ii),
                             __ldg(tm21 + base + ii), __ldg(tm22 + base + ii));
        int j5 = ii + 2, j6 = ii + 3;
        float e11 = 0.f, e12 = 0.f, e21 = 0.f, e22 = 0.f;
        float f11 = 0.f, f12 = 0.f, f21 = 0.f, f22 = 0.f;
        if (j5 < NLOD) {
            e11 = __ldg(tm11 + base + j5); e12 = __ldg(tm12 + base + j5);
            e21 = __ldg(tm21 + base + j5); e22 = __ldg(tm22 + base + j5);
        }
        if (j6 < NLOD) {
            f11 = __ldg(tm11 + base + j6); f12 = __ldg(tm12 + base + j6);
            f21 = __ldg(tm21 + base + j6); f22 = __ldg(tm22 + base + j6);
        }
        od[rr] = make_uint4(pk(e11, e12), pk(e21, e22),
                            pk(f11, f12), pk(f21, f22));
    }
    // zero both state buffers of both halves (guard cells included)
    for (int idx = tid; idx < 4 * 136; idx += 256) {
        s_st[idx] = make_float4(0.f, 0.f, 0.f, 0.f);
        s_cs[idx] = 0.f;
    }

    const float bbl  = __ldg(cb + (lane & 15));
    const float tcur = __ldg(tcu + r);
    const float tclr = __ldg(tcl + r);

    float Wu[NK], Wl[NK];
    #pragma unroll
    for (int k = 0; k < NK; k++) {
        Wu[k] = __ldg(cw + r * NK + k);
        Wl[k] = __ldg(cw + (NLOD + r) * NK + k);
    }

    // full carry in registers
    float cmu = imean[(long)b * 2 * NLOD + r];
    float cml = imean[(long)b * 2 * NLOD + NLOD + r];
    float ccu = icu[(long)b * NLOD + r];
    float ccl = icl[(long)b * NLOD + r];
    float ccs = ics[(long)b * NLOD + r];

    const float* obs_p = lobs  + ((long)b * NT) * NLOD + r;
    const float* ov_p  = ovars + ((long)b * NT) * NLOD + r;
    float obs_r = __ldg(obs_p);
    float ov_r  = __ldg(ov_p);
    obs_p += NLOD; ov_p += NLOD;

    // ---- register tables: d0 (r-3), d1 (r-2), d2 (r-1), d4 (r+1) ----
    uint4 Rab[NK], Rcd[NK];
    {
        const int j0 = r - 3, j1 = r - 2, j2 = r - 1, j4 = r + 1;
        const bool v0 = (j0 >= 0), v1 = (j1 >= 0), v2 = (j2 >= 0), v4 = (j4 < NLOD);
        #pragma unroll
        for (int k = 0; k < NK; k++) {
            long base = ((long)k * NLOD + r) * NLOD;
            float a11 = 0.f, a12 = 0.f, a21 = 0.f, a22 = 0.f;
            float b11 = 0.f, b12 = 0.f, b21 = 0.f, b22 = 0.f;
            float c11 = 0.f, c12 = 0.f, c21 = 0.f, c22 = 0.f;
            float d11 = 0.f, d12 = 0.f, d21 = 0.f, d22 = 0.f;
            if (v0) {
                a11 = __ldg(tm11 + base + j0); a12 = __ldg(tm12 + base + j0);
                a21 = __ldg(tm21 + base + j0); a22 = __ldg(tm22 + base + j0);
            }
            if (v1) {
                b11 = __ldg(tm11 + base + j1); b12 = __ldg(tm12 + base + j1);
                b21 = __ldg(tm21 + base + j1); b22 = __ldg(tm22 + base + j1);
            }
            if (v2) {
                c11 = __ldg(tm11 + base + j2); c12 = __ldg(tm12 + base + j2);
                c21 = __ldg(tm21 + base + j2); c22 = __ldg(tm22 + base + j2);
            }
            if (v4) {
                d11 = __ldg(tm11 + base + j4); d12 = __ldg(tm12 + base + j4);
                d21 = __ldg(tm21 + base + j4); d22 = __ldg(tm22 + base + j4);
            }
            Rab[k] = make_uint4(pk(a11, a12), pk(a21, a22),
                                pk(b11, b12), pk(b21, b22));
            Rcd[k] = make_uint4(pk(c11, c12), pk(c21, c22),
                                pk(d11, d12), pk(d21, d22));
        }
    }

    float* out_pm = out;
    float* out_cu = out + (long)NB * NT * 2 * NLOD;
    float* out_cl = out_cu + (long)NB * NT * NLOD;
    float* out_cs = out_cl + (long)NB * NT * NLOD;

    __syncthreads();   // tables + state zero visible to both halves

    for (int t = 0; t < NT; t++) {
        const int buf = t & 1;
        float4* stb = s_st + (half * 2 + buf) * 136;
        float*  csb = s_cs + (half * 2 + buf) * 136;
        float*  rdb = red  + (half * 2 + buf) * 64;

        // ========= phase 1: obs update + logits =========
        float rd    = frcp(ccu + ov_r);
        float qu    = ccu * rd;
        float ql    = ccs * rd;
        float res   = obs_r - cmu;
        float pu    = cmu + qu * res;
        float pl    = cml + ql * res;
        float cf    = 1.0f - qu;
        float pcu   = cf * ccu;
        float pcl   = ccl - ql * ccs;
        float pcs   = cf * ccs;

        if (t + 1 < NT) {
            obs_r = __ldg(obs_p);
            ov_r  = __ldg(ov_p);
            obs_p += NLOD; ov_p += NLOD;
        }

        stb[3 + r] = make_float4(pu, pl, pcu, pcl);
        csb[3 + r] = pcs;

        long obase = (long)b * NT + t;
        out_pm[obase * 2 * NLOD + r]        = pu;
        out_pm[obase * 2 * NLOD + NLOD + r] = pl;
        out_cu[obase * NLOD + r] = pcu;
        out_cl[obase * NLOD + r] = pcl;
        out_cs[obase * NLOD + r] = pcs;

        // logits over this batch's 128 rows (value-splitting butterfly)
        float v[NK];
        #pragma unroll
        for (int k = 0; k < NK; k++) v[k] = fmaf(pu, Wu[k], pl * Wl[k]);
        #pragma unroll
        for (int k = 0; k < NK; k++) v[k] += __shfl_xor_sync(0xffffffffu, v[k], 16);
        RED_ROUND(8)
        RED_ROUND(4)
        RED_ROUND(2)
        RED_ROUND(1)
        if (lane < 16) rdb[lane * 4 + wloc] = v[0];
        bar128(barid);   // the ONLY barrier per step (per batch)

        // ========= phase 2: softmax (deferred norm) + A-gen + matvec =========
        float w_, s_;
        {
            const float4* red4 = reinterpret_cast<const float4*>(rdb);
            float4 rp = red4[lane & 15];
            float lg = bbl + ((rp.x + rp.y) + (rp.z + rp.w));
            w_ = __expf(lg);       // unnormalized weight for k = lane&15
            s_ = w_;
            #pragma unroll
            for (int m = 8; m >= 1; m >>= 1)
                s_ += __shfl_xor_sync(0xffffffffu, s_, m);
        }

        unsigned long long P0 = 0ull, Q0 = 0ull, P1 = 0ull, Q1 = 0ull;
        unsigned long long P2 = 0ull, Q2 = 0ull, P4 = 0ull, Q4 = 0ull;
        unsigned long long P5 = 0ull, Q5 = 0ull, P6 = 0ull, Q6 = 0ull;
        float D11 = 0.f, D12 = 0.f, D21 = 0.f, D22 = 0.f;
        #pragma unroll
        for (int k = 0; k < NK; k++) {
            float a = __shfl_sync(0xffffffffu, w_, k);
            unsigned long long a2 = dup2(a);
            uint4 rab = Rab[k], rcd = Rcd[k];
            uint4 ro  = od[k * NLOD + r];
            float4 gv = dg[k * NLOD + r];
            pair_fma(P0, rab.x, a2);
            pair_fma(Q0, rab.y, a2);
            pair_fma(P1, rab.z, a2);
            pair_fma(Q1, rab.w, a2);
            pair_fma(P2, rcd.x, a2);
            pair_fma(Q2, rcd.y, a2);
            pair_fma(P4, rcd.z, a2);
            pair_fma(Q4, rcd.w, a2);
            pair_fma(P5, ro.x, a2);
            pair_fma(Q5, ro.y, a2);
            pair_fma(P6, ro.z, a2);
            pair_fma(Q6, ro.w, a2);
            D11 = fmaf(a, gv.x, D11);
            D12 = fmaf(a, gv.y, D12);
            D21 = fmaf(a, gv.z, D21);
            D22 = fmaf(a, gv.w, D22);
        }

        const float inv = frcp(s_);
        float nmu = 0.f, nml = 0.f, ncu = 0.f, ncl = 0.f, ncs = 0.f;
        float x, y, z, w2;
        unpk2(P0, x, y); unpk2(Q0, z, w2);
        BAND_NORM_ACC(0, x, y, z, w2)
        unpk2(P1, x, y); unpk2(Q1, z, w2);
        BAND_NORM_ACC(1, x, y, z, w2)
        unpk2(P2, x, y); unpk2(Q2, z, w2);
        BAND_NORM_ACC(2, x, y, z, w2)
        {   // diagonal d=3: A = D*inv + I (fp32)
            float a11 = fmaf(D11, inv, 1.0f), a12 = D12 * inv;
            float a21 = D21 * inv, a22 = fmaf(D22, inv, 1.0f);
            float4 st_ = stb[r + 3];
            float  csj = csb[r + 3];
            float muj = st_.x, mlj = st_.y, cuj = st_.z, clj = st_.w;
            nmu = fmaf(a11, muj, nmu); nmu = fmaf(a12, mlj, nmu);
            nml = fmaf(a21, muj, nml); nml = fmaf(a22, mlj, nml);
            ncu = fmaf(a11 * a11, cuj, ncu);
            ncu = fmaf(2.0f * a11 * a12, csj, ncu);
            ncu = fmaf(a12 * a12, clj, ncu);
            ncl = fmaf(a21 * a21, cuj, ncl);
            ncl = fmaf(2.0f * a21 * a22, csj, ncl);
            ncl = fmaf(a22 * a22, clj, ncl);
            ncs = fmaf(a21 * a11, cuj, ncs);
            ncs = fmaf(fmaf(a22, a11, a21 * a12), csj, ncs);
            ncs = fmaf(a22 * a12, clj, ncs);
        }
        unpk2(P4, x, y); unpk2(Q4, z, w2);
        BAND_NORM_ACC(4, x, y, z, w2)
        unpk2(P5, x, y); unpk2(Q5, z, w2);
        BAND_NORM_ACC(5, x, y, z, w2)
        unpk2(P6, x, y); unpk2(Q6, z, w2);
        BAND_NORM_ACC(6, x, y, z, w2)

        cmu = nmu; cml = nml;
        ccu = ncu + tcur; ccl = ncl + tclr; ccs = ncs;
        // no second barrier: next phase-1 writes the OTHER buffer
    }
}

extern "C" void kernel_launch(void* const* d_in, const int* in_sizes, int n_in,
                              void* d_out, int out_size)
{
    (void)in_sizes; (void)n_in; (void)out_size;
    const float* lobs  = (const float*)d_in[0];
    const float* ovars = (const float*)d_in[1];
    const float* imean = (const float*)d_in[2];
    const float* icu   = (const float*)d_in[3];
    const float* icl   = (const float*)d_in[4];
    const float* ics   = (const float*)d_in[5];
    const float* tm11  = (const float*)d_in[6];
    const float* tm12  = (const float*)d_in[7];
    const float* tm21  = (const float*)d_in[8];
    const float* tm22  = (const float*)d_in[9];
    const float* cw    = (const float*)d_in[10];
    const float* cb    = (const float*)d_in[11];
    const float* tcu   = (const float*)d_in[12];
    const float* tcl   = (const float*)d_in[13];
    float* out = (float*)d_out;

    cudaFuncSetAttribute(rkn_kernel,
                         cudaFuncAttributeMaxDynamicSharedMemorySize, SMEM_BYTES);

    rkn_kernel<<<NB / 2, 256, SMEM_BYTES>>>(lobs, ovars, imean, icu, icl, ics,
                                            tm11, tm12, tm21, tm22,
                                            cw, cb, tcu, tcl, out);
}